// round 13
// baseline (speedup 1.0000x reference)
#include <cuda_runtime.h>
#include <cuda_bf16.h>
#include <cstdint>
#include <math.h>

#define ROWS 8192
#define COLS 256
#define KS 64                     /* screen features */
#define BM 128
#define BN 128
#define KSTEPS 4                  /* 64 / 16 per bf16 mma */
#define TILES 64                  /* 8192/128 */
#define NTRI (TILES * (TILES + 1) / 2)  /* 2080 */
#define NFULL (TILES * TILES)           /* 4096 */
#define NBLK (2 * NTRI + NFULL)         /* 8256 */
#define SCREEN_THRESH 50.0f
#define A_BYTES (BM * KS * 2)     /* 16384 */
#define DYN_SMEM (2 * A_BYTES)    /* 32768 */

// ---------------------------------------------------------------------------
// device scratch
// ---------------------------------------------------------------------------
__device__ __align__(16) __nv_bfloat16 g_Nbf[ROWS * KS];   // first 64 dims
__device__ __align__(16) __nv_bfloat16 g_Rbf[ROWS * KS];
__device__ float g_x2hN[ROWS];   // partial norms (first 64 dims, screen)
__device__ float g_x2hR[ROWS];
__device__ float g_x2N[ROWS];    // full norms (exact path)
__device__ float g_x2R[ROWS];
__device__ float g_part[NBLK];
__device__ unsigned g_done = 0;  // ticket counter (self-resetting)

// ---------------------------------------------------------------------------
// PTX helpers (base-arch only)
// ---------------------------------------------------------------------------
__device__ __forceinline__ uint32_t smem_u32(const void* p) {
    uint32_t a;
    asm("{ .reg .u64 t; cvta.to.shared.u64 t, %1; cvt.u32.u64 %0, t; }" : "=r"(a) : "l"(p));
    return a;
}
#define CP16(dst, src) \
    asm volatile("cp.async.cg.shared.global [%0], [%1], 16;" :: "r"(dst), "l"(src) : "memory")
#define LDSM4(r, addr) \
    asm volatile("ldmatrix.sync.aligned.m8n8.x4.shared.b16 {%0,%1,%2,%3}, [%4];" \
        : "=r"((r)[0]), "=r"((r)[1]), "=r"((r)[2]), "=r"((r)[3]) : "r"(addr))
#define LDSM2(r, addr) \
    asm volatile("ldmatrix.sync.aligned.m8n8.x2.shared.b16 {%0,%1}, [%2];" \
        : "=r"((r)[0]), "=r"((r)[1]) : "r"(addr))
#define MMA16816(d, a, b) \
    asm volatile("mma.sync.aligned.m16n8k16.row.col.f32.bf16.bf16.f32 " \
        "{%0,%1,%2,%3}, {%4,%5,%6,%7}, {%8,%9}, {%0,%1,%2,%3};" \
        : "+f"((d)[0]), "+f"((d)[1]), "+f"((d)[2]), "+f"((d)[3]) \
        : "r"((a)[0]), "r"((a)[1]), "r"((a)[2]), "r"((a)[3]), "r"((b)[0]), "r"((b)[1]))

// tile row = 64 bf16 = 128 B = 8 x 16B chunks; XOR swizzle over the 8 phases
#define SWOFF8(row, chunk) ((uint32_t)(((row) * 8 + ((chunk) ^ ((row) & 7))) * 16))

// ---------------------------------------------------------------------------
// Prep: bf16 image of first 64 dims + partial/full fp32 row norms.
// One warp per row.
// ---------------------------------------------------------------------------
__global__ void prep_kernel(const float* __restrict__ Nf, const float* __restrict__ Rf) {
    const float* src = blockIdx.y ? Rf : Nf;
    __nv_bfloat16* dst = blockIdx.y ? g_Rbf : g_Nbf;
    float* x2h = blockIdx.y ? g_x2hR : g_x2hN;
    float* x2f = blockIdx.y ? g_x2R : g_x2N;

    int row = blockIdx.x * 8 + (threadIdx.x >> 5);
    int lane = threadIdx.x & 31;
    const float* p = src + (size_t)row * COLS + lane * 8;
    float4 v0 = *(const float4*)p;
    float4 v1 = *(const float4*)(p + 4);
    float s = 0.f;
    s = fmaf(v0.x, v0.x, s); s = fmaf(v0.y, v0.y, s);
    s = fmaf(v0.z, v0.z, s); s = fmaf(v0.w, v0.w, s);
    s = fmaf(v1.x, v1.x, s); s = fmaf(v1.y, v1.y, s);
    s = fmaf(v1.z, v1.z, s); s = fmaf(v1.w, v1.w, s);

    if (lane < 8) {    // first 64 dims -> bf16 image (8 bf16 per lane)
        __align__(16) __nv_bfloat16 b[8];
        b[0] = __float2bfloat16(v0.x); b[1] = __float2bfloat16(v0.y);
        b[2] = __float2bfloat16(v0.z); b[3] = __float2bfloat16(v0.w);
        b[4] = __float2bfloat16(v1.x); b[5] = __float2bfloat16(v1.y);
        b[6] = __float2bfloat16(v1.z); b[7] = __float2bfloat16(v1.w);
        *(uint4*)(dst + (size_t)row * KS + lane * 8) = *(const uint4*)b;
    }

    float sh = (lane < 8) ? s : 0.f;
#pragma unroll
    for (int o = 16; o > 0; o >>= 1) {
        s  += __shfl_xor_sync(0xffffffffu, s, o);
        sh += __shfl_xor_sync(0xffffffffu, sh, o);
    }
    if (lane == 0) { x2f[row] = s; x2h[row] = sh; }
}

// ---------------------------------------------------------------------------
// bf16 HMMA K=64 Gram screen + exact fp32 epilogue + fused last-block finalize.
// ---------------------------------------------------------------------------
__global__ __launch_bounds__(256)
void mmd_mma_kernel(const float* __restrict__ Nf, const float* __restrict__ Rf,
                    float* __restrict__ out) {
    const int bid = blockIdx.x;

    int pass, ti, tj;
    if (bid < 2 * NTRI) {
        pass = bid < NTRI ? 0 : 1;
        int idx = bid - pass * NTRI;
        int r = 0;
        while (idx >= TILES - r) { idx -= TILES - r; r++; }
        ti = r; tj = r + idx;
    } else {
        pass = 2;
        int q = bid - 2 * NTRI;
        ti = q >> 6; tj = q & 63;
    }
    const bool sym = (pass < 2);

    const __nv_bfloat16 *Abf, *Bbf;
    const float *x2ha, *x2hb, *x2a, *x2b, *Af, *Bf;
    if (pass == 0)      { Abf = g_Nbf; Bbf = g_Nbf; x2ha = g_x2hN; x2hb = g_x2hN;
                          x2a = g_x2N; x2b = g_x2N; Af = Nf; Bf = Nf; }
    else if (pass == 1) { Abf = g_Rbf; Bbf = g_Rbf; x2ha = g_x2hR; x2hb = g_x2hR;
                          x2a = g_x2R; x2b = g_x2R; Af = Rf; Bf = Rf; }
    else                { Abf = g_Nbf; Bbf = g_Rbf; x2ha = g_x2hN; x2hb = g_x2hR;
                          x2a = g_x2N; x2b = g_x2R; Af = Nf; Bf = Rf; }

    extern __shared__ uint8_t dynsmem[];
    __shared__ float wsum[8];
    __shared__ bool isLast;
    const int tid = threadIdx.x, wid = tid >> 5, lane = tid & 31;
    const uint32_t aS = smem_u32(dynsmem);
    const uint32_t bS = aS + A_BYTES;

    // ---- single load phase: rows are 128B = 8 chunks; 8 threads/row ----
    {
        const int chunk = tid & 7;
        const int rbase = tid >> 3;           // 0..31
        const uint8_t* Ag = (const uint8_t*)(Abf + (size_t)(ti * BM) * KS);
        const uint8_t* Bg = (const uint8_t*)(Bbf + (size_t)(tj * BN) * KS);
#pragma unroll
        for (int u = 0; u < 4; u++) {
            int row = rbase + u * 32;
            CP16(aS + SWOFF8(row, chunk), Ag + (size_t)row * (KS * 2) + chunk * 16);
            CP16(bS + SWOFF8(row, chunk), Bg + (size_t)row * (KS * 2) + chunk * 16);
        }
        asm volatile("cp.async.commit_group;" ::: "memory");
        asm volatile("cp.async.wait_group 0;" ::: "memory");
        __syncthreads();
    }

    float acc[4][4][4];
#pragma unroll
    for (int mi = 0; mi < 4; mi++)
#pragma unroll
        for (int ni = 0; ni < 4; ni++)
#pragma unroll
            for (int r = 0; r < 4; r++) acc[mi][ni][r] = 0.f;

    const int wm = (wid & 1) * 64;            // warp tile 64x32, layout 2x4
    const int wn = (wid >> 1) * 32;
    const int a_r = lane & 15, a_c = lane >> 4;
    const int b_r = lane & 7,  b_c = (lane >> 3) & 1;

    // ---- mainloop: zero barriers, 4 k-steps x 16 MMA ----
#pragma unroll 1
    for (int k = 0; k < KSTEPS; k++) {
        uint32_t a_frag[4][4], b_frag[4][2];
#pragma unroll
        for (int mi = 0; mi < 4; mi++)
            LDSM4(a_frag[mi], aS + SWOFF8(wm + mi * 16 + a_r, 2 * k + a_c));
#pragma unroll
        for (int ni = 0; ni < 4; ni++)
            LDSM2(b_frag[ni], bS + SWOFF8(wn + ni * 8 + b_r, 2 * k + b_c));
#pragma unroll
        for (int mi = 0; mi < 4; mi++)
#pragma unroll
            for (int ni = 0; ni < 4; ni++)
                MMA16816(acc[mi][ni], a_frag[mi], b_frag[ni]);
    }

    // ---- epilogue: partial-d2 screen; exact fp32 full-K recompute on pass ----
    const int qr = lane >> 2, qc = (lane & 3) * 2;
    float x2i[8], x2j[8];
#pragma unroll
    for (int mi = 0; mi < 4; mi++) {
        x2i[mi * 2 + 0] = x2ha[ti * BM + wm + mi * 16 + qr];
        x2i[mi * 2 + 1] = x2ha[ti * BM + wm + mi * 16 + qr + 8];
    }
#pragma unroll
    for (int ni = 0; ni < 4; ni++) {
        x2j[ni * 2 + 0] = x2hb[tj * BN + wn + ni * 8 + qc];
        x2j[ni * 2 + 1] = x2hb[tj * BN + wn + ni * 8 + qc + 1];
    }

    const bool diag = sym && (ti == tj);
    const float base_w = sym ? 2.f : 1.f;
    float ssum = 0.f;
#pragma unroll
    for (int mi = 0; mi < 4; mi++) {
#pragma unroll
        for (int ni = 0; ni < 4; ni++) {
#pragma unroll
            for (int r = 0; r < 4; r++) {
                // partial d^2 over first 64 dims (lower bound of full d^2)
                float d2p = fmaf(-2.f, acc[mi][ni][r],
                                 x2i[mi * 2 + (r >> 1)] + x2j[ni * 2 + (r & 1)]);
                if (d2p < SCREEN_THRESH) {
                    int i = ti * BM + wm + mi * 16 + qr + (r >> 1) * 8;
                    int j = tj * BN + wn + ni * 8 + qc + (r & 1);
                    const float* ar = Af + (size_t)i * COLS;
                    const float* br = Bf + (size_t)j * COLS;
                    float pd = 0.f;
                    for (int k = 0; k < COLS; k += 4) {
                        float4 av = *(const float4*)(ar + k);
                        float4 bv = *(const float4*)(br + k);
                        pd = fmaf(av.x, bv.x, pd); pd = fmaf(av.y, bv.y, pd);
                        pd = fmaf(av.z, bv.z, pd); pd = fmaf(av.w, bv.w, pd);
                    }
                    float x2s = x2a[i] + x2b[j];
                    float d2f = fmaxf(fmaf(-2.f, pd, x2s), 0.f);
                    float w = base_w;
                    if (diag) w = (j > i) ? 2.f : ((j == i) ? 1.f : 0.f);
                    ssum += w * __expf(-d2f);
                }
            }
        }
    }

    // deterministic block reduction -> fixed slot
#pragma unroll
    for (int o = 16; o > 0; o >>= 1) ssum += __shfl_xor_sync(0xffffffffu, ssum, o);
    if (lane == 0) wsum[wid] = ssum;
    __syncthreads();
    if (tid == 0) {
        float t = 0.f;
#pragma unroll
        for (int w = 0; w < 8; w++) t += wsum[w];
        g_part[bid] = t;
        __threadfence();
        unsigned v = atomicAdd(&g_done, 1u);
        isLast = (v == NBLK - 1);
    }
    __syncthreads();

    // ---- fused finalize: last CTA sweeps all partials (fixed order) ----
    if (isLast) {
        float* sh0 = (float*)dynsmem;             // reuse tile smem
        float* sh1 = sh0 + 256;
        float* sh2 = sh1 + 256;
        float s0 = 0.f, s1 = 0.f, s2 = 0.f;
        for (int idx = tid; idx < NBLK; idx += 256) {
            float v = g_part[idx];
            if (idx < NTRI) s0 += v;
            else if (idx < 2 * NTRI) s1 += v;
            else s2 += v;
        }
        sh0[tid] = s0; sh1[tid] = s1; sh2[tid] = s2;
        __syncthreads();
        for (int o = 128; o > 0; o >>= 1) {
            if (tid < o) {
                sh0[tid] += sh0[tid + o];
                sh1[tid] += sh1[tid + o];
                sh2[tid] += sh2[tid + o];
            }
            __syncthreads();
        }
        if (tid == 0) {
            double inv = 1.0 / ((double)ROWS * (double)ROWS);
            double mmd = ((double)sh0[0] + (double)sh1[0] - 2.0 * (double)sh2[0]) * inv;
            if (mmd < 0.0) mmd = 0.0;
            out[0] = (float)sqrt(mmd);
            g_done = 0;            // reset for next (graph-replayed) launch
        }
    }
}

// ---------------------------------------------------------------------------
extern "C" void kernel_launch(void* const* d_in, const int* in_sizes, int n_in,
                              void* d_out, int out_size) {
    const float* Nf = (const float*)d_in[0];
    const float* Rf = (const float*)d_in[1];
    float* out = (float*)d_out;
    (void)in_sizes; (void)n_in; (void)out_size;

    cudaFuncSetAttribute(mmd_mma_kernel,
                         cudaFuncAttributeMaxDynamicSharedMemorySize, DYN_SMEM);

    dim3 pgrid(ROWS / 8, 2, 1);
    prep_kernel<<<pgrid, 256>>>(Nf, Rf);

    mmd_mma_kernel<<<NBLK, 256, DYN_SMEM>>>(Nf, Rf, out);
}

// round 14
// speedup vs baseline: 1.3138x; 1.3138x over previous
#include <cuda_runtime.h>
#include <cuda_bf16.h>
#include <cstdint>
#include <math.h>

#define ROWS 8192
#define COLS 256
#define KS 64                     /* screen features */
#define BM 64
#define BN 128
#define KSTEPS 4                  /* 64 / 16 per bf16 mma */
#define TM_TILES 128              /* 8192/64 */
#define TN_TILES 64               /* 8192/128 */
#define NSYM 4160                 /* sum_{ti} (64 - ti/2) */
#define NFULL (TM_TILES * TN_TILES)     /* 8192 */
#define NBLK (2 * NSYM + NFULL)         /* 16512 */
#define SCREEN_THRESH 50.0f
#define A_BYTES (BM * KS * 2)     /* 8192 */
#define B_BYTES (BN * KS * 2)     /* 16384 */
#define DYN_SMEM (A_BYTES + B_BYTES)    /* 24576 */

// ---------------------------------------------------------------------------
// device scratch
// ---------------------------------------------------------------------------
__device__ __align__(16) __nv_bfloat16 g_Nbf[ROWS * KS];   // first 64 dims
__device__ __align__(16) __nv_bfloat16 g_Rbf[ROWS * KS];
__device__ float g_x2hN[ROWS];   // partial norms (first 64 dims, screen)
__device__ float g_x2hR[ROWS];
__device__ float g_x2N[ROWS];    // full norms (exact path)
__device__ float g_x2R[ROWS];
__device__ float g_part[NBLK];

// ---------------------------------------------------------------------------
// PTX helpers (base-arch only)
// ---------------------------------------------------------------------------
__device__ __forceinline__ uint32_t smem_u32(const void* p) {
    uint32_t a;
    asm("{ .reg .u64 t; cvta.to.shared.u64 t, %1; cvt.u32.u64 %0, t; }" : "=r"(a) : "l"(p));
    return a;
}
#define CP16(dst, src) \
    asm volatile("cp.async.cg.shared.global [%0], [%1], 16;" :: "r"(dst), "l"(src) : "memory")
#define LDSM4(r, addr) \
    asm volatile("ldmatrix.sync.aligned.m8n8.x4.shared.b16 {%0,%1,%2,%3}, [%4];" \
        : "=r"((r)[0]), "=r"((r)[1]), "=r"((r)[2]), "=r"((r)[3]) : "r"(addr))
#define LDSM2(r, addr) \
    asm volatile("ldmatrix.sync.aligned.m8n8.x2.shared.b16 {%0,%1}, [%2];" \
        : "=r"((r)[0]), "=r"((r)[1]) : "r"(addr))
#define MMA16816(d, a, b) \
    asm volatile("mma.sync.aligned.m16n8k16.row.col.f32.bf16.bf16.f32 " \
        "{%0,%1,%2,%3}, {%4,%5,%6,%7}, {%8,%9}, {%0,%1,%2,%3};" \
        : "+f"((d)[0]), "+f"((d)[1]), "+f"((d)[2]), "+f"((d)[3]) \
        : "r"((a)[0]), "r"((a)[1]), "r"((a)[2]), "r"((a)[3]), "r"((b)[0]), "r"((b)[1]))

// tile row = 64 bf16 = 128 B = 8 x 16B chunks; XOR swizzle over the 8 phases
#define SWOFF8(row, chunk) ((uint32_t)(((row) * 8 + ((chunk) ^ ((row) & 7))) * 16))

// ---------------------------------------------------------------------------
// Prep: bf16 image of first 64 dims + partial/full fp32 row norms.
// One warp per row.
// ---------------------------------------------------------------------------
__global__ void prep_kernel(const float* __restrict__ Nf, const float* __restrict__ Rf) {
    const float* src = blockIdx.y ? Rf : Nf;
    __nv_bfloat16* dst = blockIdx.y ? g_Rbf : g_Nbf;
    float* x2h = blockIdx.y ? g_x2hR : g_x2hN;
    float* x2f = blockIdx.y ? g_x2R : g_x2N;

    int row = blockIdx.x * 8 + (threadIdx.x >> 5);
    int lane = threadIdx.x & 31;
    const float* p = src + (size_t)row * COLS + lane * 8;
    float4 v0 = *(const float4*)p;
    float4 v1 = *(const float4*)(p + 4);
    float s = 0.f;
    s = fmaf(v0.x, v0.x, s); s = fmaf(v0.y, v0.y, s);
    s = fmaf(v0.z, v0.z, s); s = fmaf(v0.w, v0.w, s);
    s = fmaf(v1.x, v1.x, s); s = fmaf(v1.y, v1.y, s);
    s = fmaf(v1.z, v1.z, s); s = fmaf(v1.w, v1.w, s);

    if (lane < 8) {    // first 64 dims -> bf16 image (8 bf16 per lane)
        __align__(16) __nv_bfloat16 b[8];
        b[0] = __float2bfloat16(v0.x); b[1] = __float2bfloat16(v0.y);
        b[2] = __float2bfloat16(v0.z); b[3] = __float2bfloat16(v0.w);
        b[4] = __float2bfloat16(v1.x); b[5] = __float2bfloat16(v1.y);
        b[6] = __float2bfloat16(v1.z); b[7] = __float2bfloat16(v1.w);
        *(uint4*)(dst + (size_t)row * KS + lane * 8) = *(const uint4*)b;
    }

    float sh = (lane < 8) ? s : 0.f;
#pragma unroll
    for (int o = 16; o > 0; o >>= 1) {
        s  += __shfl_xor_sync(0xffffffffu, s, o);
        sh += __shfl_xor_sync(0xffffffffu, sh, o);
    }
    if (lane == 0) { x2f[row] = s; x2h[row] = sh; }
}

// ---------------------------------------------------------------------------
// bf16 HMMA K=64 Gram screen + exact fp32 epilogue, 64x128 CTA tile.
// 8 warps (2m x 4n), warp tile 32x32 -> 32-reg accumulators, 3 CTAs/SM.
// Sym passes keep only tiles with tj >= ti/2 (rest fully below diagonal).
// ---------------------------------------------------------------------------
__global__ __launch_bounds__(256, 3)
void mmd_mma_kernel(const float* __restrict__ Nf, const float* __restrict__ Rf) {
    const int bid = blockIdx.x;

    int pass, ti, tj;
    if (bid < 2 * NSYM) {
        pass = bid < NSYM ? 0 : 1;
        int idx = bid - pass * NSYM;
        // rows come in pairs (2m, 2m+1), each with 64-m jobs starting at tj=m
        int m = 0;
        while (idx >= 2 * (64 - m)) { idx -= 2 * (64 - m); m++; }
        int second = idx >= (64 - m);
        if (second) idx -= (64 - m);
        ti = 2 * m + second;
        tj = m + idx;
    } else {
        pass = 2;
        int q = bid - 2 * NSYM;
        ti = q >> 6; tj = q & 63;
    }
    const bool sym = (pass < 2);

    const __nv_bfloat16 *Abf, *Bbf;
    const float *x2ha, *x2hb, *x2a, *x2b, *Af, *Bf;
    if (pass == 0)      { Abf = g_Nbf; Bbf = g_Nbf; x2ha = g_x2hN; x2hb = g_x2hN;
                          x2a = g_x2N; x2b = g_x2N; Af = Nf; Bf = Nf; }
    else if (pass == 1) { Abf = g_Rbf; Bbf = g_Rbf; x2ha = g_x2hR; x2hb = g_x2hR;
                          x2a = g_x2R; x2b = g_x2R; Af = Rf; Bf = Rf; }
    else                { Abf = g_Nbf; Bbf = g_Rbf; x2ha = g_x2hN; x2hb = g_x2hR;
                          x2a = g_x2N; x2b = g_x2R; Af = Nf; Bf = Rf; }

    extern __shared__ uint8_t dynsmem[];
    __shared__ float wsum[8];
    const int tid = threadIdx.x, wid = tid >> 5, lane = tid & 31;
    const uint32_t aS = smem_u32(dynsmem);
    const uint32_t bS = aS + A_BYTES;

    // ---- single load phase: rows are 128B = 8 chunks; 8 threads/row ----
    {
        const int chunk = tid & 7;
        const int rbase = tid >> 3;           // 0..31
        const uint8_t* Ag = (const uint8_t*)(Abf + (size_t)(ti * BM) * KS);
        const uint8_t* Bg = (const uint8_t*)(Bbf + (size_t)(tj * BN) * KS);
#pragma unroll
        for (int u = 0; u < 2; u++) {         // A: 64 rows
            int row = rbase + u * 32;
            CP16(aS + SWOFF8(row, chunk), Ag + (size_t)row * (KS * 2) + chunk * 16);
        }
#pragma unroll
        for (int u = 0; u < 4; u++) {         // B: 128 rows
            int row = rbase + u * 32;
            CP16(bS + SWOFF8(row, chunk), Bg + (size_t)row * (KS * 2) + chunk * 16);
        }
        asm volatile("cp.async.commit_group;" ::: "memory");
        asm volatile("cp.async.wait_group 0;" ::: "memory");
        __syncthreads();
    }

    float acc[2][4][4];
#pragma unroll
    for (int mi = 0; mi < 2; mi++)
#pragma unroll
        for (int ni = 0; ni < 4; ni++)
#pragma unroll
            for (int r = 0; r < 4; r++) acc[mi][ni][r] = 0.f;

    const int wm = (wid & 1) * 32;            // warp tile 32x32, layout 2x4
    const int wn = (wid >> 1) * 32;
    const int a_r = lane & 15, a_c = lane >> 4;
    const int b_r = lane & 7,  b_c = (lane >> 3) & 1;

    // ---- mainloop: zero barriers, 4 k-steps x 8 MMA ----
#pragma unroll 1
    for (int k = 0; k < KSTEPS; k++) {
        uint32_t a_frag[2][4], b_frag[4][2];
#pragma unroll
        for (int mi = 0; mi < 2; mi++)
            LDSM4(a_frag[mi], aS + SWOFF8(wm + mi * 16 + a_r, 2 * k + a_c));
#pragma unroll
        for (int ni = 0; ni < 4; ni++)
            LDSM2(b_frag[ni], bS + SWOFF8(wn + ni * 8 + b_r, 2 * k + b_c));
#pragma unroll
        for (int mi = 0; mi < 2; mi++)
#pragma unroll
            for (int ni = 0; ni < 4; ni++)
                MMA16816(acc[mi][ni], a_frag[mi], b_frag[ni]);
    }

    // ---- epilogue: partial-d2 screen; exact fp32 full-K recompute on pass ----
    const int qr = lane >> 2, qc = (lane & 3) * 2;
    float x2i[4], x2j[8];
#pragma unroll
    for (int mi = 0; mi < 2; mi++) {
        x2i[mi * 2 + 0] = x2ha[ti * BM + wm + mi * 16 + qr];
        x2i[mi * 2 + 1] = x2ha[ti * BM + wm + mi * 16 + qr + 8];
    }
#pragma unroll
    for (int ni = 0; ni < 4; ni++) {
        x2j[ni * 2 + 0] = x2hb[tj * BN + wn + ni * 8 + qc];
        x2j[ni * 2 + 1] = x2hb[tj * BN + wn + ni * 8 + qc + 1];
    }

    const bool diag = sym && (tj == (ti >> 1));   // tile intersects the diagonal
    const float base_w = sym ? 2.f : 1.f;
    float ssum = 0.f;
#pragma unroll
    for (int mi = 0; mi < 2; mi++) {
#pragma unroll
        for (int ni = 0; ni < 4; ni++) {
#pragma unroll
            for (int r = 0; r < 4; r++) {
                // partial d^2 over first 64 dims (lower bound of full d^2)
                float d2p = fmaf(-2.f, acc[mi][ni][r],
                                 x2i[mi * 2 + (r >> 1)] + x2j[ni * 2 + (r & 1)]);
                if (d2p < SCREEN_THRESH) {
                    int i = ti * BM + wm + mi * 16 + qr + (r >> 1) * 8;
                    int j = tj * BN + wn + ni * 8 + qc + (r & 1);
                    const float* ar = Af + (size_t)i * COLS;
                    const float* br = Bf + (size_t)j * COLS;
                    float pd = 0.f;
                    for (int k = 0; k < COLS; k += 4) {
                        float4 av = *(const float4*)(ar + k);
                        float4 bv = *(const float4*)(br + k);
                        pd = fmaf(av.x, bv.x, pd); pd = fmaf(av.y, bv.y, pd);
                        pd = fmaf(av.z, bv.z, pd); pd = fmaf(av.w, bv.w, pd);
                    }
                    float x2s = x2a[i] + x2b[j];
                    float d2f = fmaxf(fmaf(-2.f, pd, x2s), 0.f);
                    float w = base_w;
                    if (diag) w = (j > i) ? 2.f : ((j == i) ? 1.f : 0.f);
                    ssum += w * __expf(-d2f);
                }
            }
        }
    }

    // deterministic block reduction
#pragma unroll
    for (int o = 16; o > 0; o >>= 1) ssum += __shfl_xor_sync(0xffffffffu, ssum, o);
    if (lane == 0) wsum[wid] = ssum;
    __syncthreads();
    if (tid == 0) {
        float t = 0.f;
#pragma unroll
        for (int w = 0; w < 8; w++) t += wsum[w];
        g_part[bid] = t;
    }
}

// ---------------------------------------------------------------------------
// Final deterministic reduction + sqrt (single sweep, 3 accumulators).
// Slot ranges: [0,4160) NN, [4160,8320) RR, [8320,16512) NR.
// ---------------------------------------------------------------------------
__global__ void finalize_kernel(float* __restrict__ out) {
    __shared__ float sh0[256], sh1[256], sh2[256];
    const int tid = threadIdx.x;
    float s0 = 0.f, s1 = 0.f, s2 = 0.f;
    for (int idx = tid; idx < NBLK; idx += 256) {
        float v = g_part[idx];
        if (idx < NSYM) s0 += v;
        else if (idx < 2 * NSYM) s1 += v;
        else s2 += v;
    }
    sh0[tid] = s0; sh1[tid] = s1; sh2[tid] = s2;
    __syncthreads();
    for (int o = 128; o > 0; o >>= 1) {
        if (tid < o) {
            sh0[tid] += sh0[tid + o];
            sh1[tid] += sh1[tid + o];
            sh2[tid] += sh2[tid + o];
        }
        __syncthreads();
    }
    if (tid == 0) {
        double inv = 1.0 / ((double)ROWS * (double)ROWS);
        double mmd = ((double)sh0[0] + (double)sh1[0] - 2.0 * (double)sh2[0]) * inv;
        if (mmd < 0.0) mmd = 0.0;
        out[0] = (float)sqrt(mmd);
    }
}

// ---------------------------------------------------------------------------
extern "C" void kernel_launch(void* const* d_in, const int* in_sizes, int n_in,
                              void* d_out, int out_size) {
    const float* Nf = (const float*)d_in[0];
    const float* Rf = (const float*)d_in[1];
    float* out = (float*)d_out;
    (void)in_sizes; (void)n_in; (void)out_size;

    cudaFuncSetAttribute(mmd_mma_kernel,
                         cudaFuncAttributeMaxDynamicSharedMemorySize, DYN_SMEM);

    dim3 pgrid(ROWS / 8, 2, 1);
    prep_kernel<<<pgrid, 256>>>(Nf, Rf);

    mmd_mma_kernel<<<NBLK, 256, DYN_SMEM>>>(Nf, Rf);

    finalize_kernel<<<1, 256>>>(out);
}

// round 15
// speedup vs baseline: 1.4399x; 1.0960x over previous
#include <cuda_runtime.h>
#include <cuda_bf16.h>
#include <cstdint>
#include <math.h>

#define ROWS 8192
#define COLS 256
#define KS 64                     /* screen features */
#define BM 64
#define BN 128
#define KSTEPS 4                  /* 64 / 16 per bf16 mma */
#define TM_TILES 128              /* 8192/64 */
#define TN_TILES 64               /* 8192/128 */
#define NSYM 4160                 /* sum_{ti} (64 - ti/2) */
#define NFULL (TM_TILES * TN_TILES)     /* 8192 */
#define NBLK (2 * NSYM + NFULL)         /* 16512 */
#define SCREEN_THRESH 50.0f
#define A_BYTES (BM * KS * 2)     /* 8192 */
#define B_BYTES (BN * KS * 2)     /* 16384 */
#define DYN_SMEM (A_BYTES + B_BYTES)    /* 24576 */

// ---------------------------------------------------------------------------
// device scratch
// ---------------------------------------------------------------------------
__device__ __align__(16) __nv_bfloat16 g_Nbf[ROWS * KS];   // first 64 dims
__device__ __align__(16) __nv_bfloat16 g_Rbf[ROWS * KS];
__device__ float g_x2hN[ROWS];   // partial norms (first 64 dims, screen)
__device__ float g_x2hR[ROWS];
__device__ float g_x2N[ROWS];    // full norms (exact path)
__device__ float g_x2R[ROWS];
__device__ float g_part[NBLK];

// ---------------------------------------------------------------------------
// PTX helpers (base-arch only)
// ---------------------------------------------------------------------------
__device__ __forceinline__ uint32_t smem_u32(const void* p) {
    uint32_t a;
    asm("{ .reg .u64 t; cvta.to.shared.u64 t, %1; cvt.u32.u64 %0, t; }" : "=r"(a) : "l"(p));
    return a;
}
#define CP16(dst, src) \
    asm volatile("cp.async.cg.shared.global [%0], [%1], 16;" :: "r"(dst), "l"(src) : "memory")
#define LDSM4(r, addr) \
    asm volatile("ldmatrix.sync.aligned.m8n8.x4.shared.b16 {%0,%1,%2,%3}, [%4];" \
        : "=r"((r)[0]), "=r"((r)[1]), "=r"((r)[2]), "=r"((r)[3]) : "r"(addr))
#define LDSM2(r, addr) \
    asm volatile("ldmatrix.sync.aligned.m8n8.x2.shared.b16 {%0,%1}, [%2];" \
        : "=r"((r)[0]), "=r"((r)[1]) : "r"(addr))
#define MMA16816(d, a, b) \
    asm volatile("mma.sync.aligned.m16n8k16.row.col.f32.bf16.bf16.f32 " \
        "{%0,%1,%2,%3}, {%4,%5,%6,%7}, {%8,%9}, {%0,%1,%2,%3};" \
        : "+f"((d)[0]), "+f"((d)[1]), "+f"((d)[2]), "+f"((d)[3]) \
        : "r"((a)[0]), "r"((a)[1]), "r"((a)[2]), "r"((a)[3]), "r"((b)[0]), "r"((b)[1]))

// tile row = 64 bf16 = 128 B = 8 x 16B chunks; XOR swizzle over the 8 phases
#define SWOFF8(row, chunk) ((uint32_t)(((row) * 8 + ((chunk) ^ ((row) & 7))) * 16))

// ---------------------------------------------------------------------------
// Prep: bf16 image of first 64 dims + partial/full fp32 row norms.
// One warp per row.
// ---------------------------------------------------------------------------
__global__ void prep_kernel(const float* __restrict__ Nf, const float* __restrict__ Rf) {
    const float* src = blockIdx.y ? Rf : Nf;
    __nv_bfloat16* dst = blockIdx.y ? g_Rbf : g_Nbf;
    float* x2h = blockIdx.y ? g_x2hR : g_x2hN;
    float* x2f = blockIdx.y ? g_x2R : g_x2N;

    int row = blockIdx.x * 8 + (threadIdx.x >> 5);
    int lane = threadIdx.x & 31;
    const float* p = src + (size_t)row * COLS + lane * 8;
    float4 v0 = *(const float4*)p;
    float4 v1 = *(const float4*)(p + 4);
    float s = 0.f;
    s = fmaf(v0.x, v0.x, s); s = fmaf(v0.y, v0.y, s);
    s = fmaf(v0.z, v0.z, s); s = fmaf(v0.w, v0.w, s);
    s = fmaf(v1.x, v1.x, s); s = fmaf(v1.y, v1.y, s);
    s = fmaf(v1.z, v1.z, s); s = fmaf(v1.w, v1.w, s);

    if (lane < 8) {    // first 64 dims -> bf16 image (8 bf16 per lane)
        __align__(16) __nv_bfloat16 b[8];
        b[0] = __float2bfloat16(v0.x); b[1] = __float2bfloat16(v0.y);
        b[2] = __float2bfloat16(v0.z); b[3] = __float2bfloat16(v0.w);
        b[4] = __float2bfloat16(v1.x); b[5] = __float2bfloat16(v1.y);
        b[6] = __float2bfloat16(v1.z); b[7] = __float2bfloat16(v1.w);
        *(uint4*)(dst + (size_t)row * KS + lane * 8) = *(const uint4*)b;
    }

    float sh = (lane < 8) ? s : 0.f;
#pragma unroll
    for (int o = 16; o > 0; o >>= 1) {
        s  += __shfl_xor_sync(0xffffffffu, s, o);
        sh += __shfl_xor_sync(0xffffffffu, sh, o);
    }
    if (lane == 0) { x2f[row] = s; x2h[row] = sh; }
}

// ---------------------------------------------------------------------------
// bf16 HMMA K=64 Gram screen + exact fp32 epilogue, 64x128 CTA tile.
// 8 warps (2m x 4n), warp tile 32x32 -> 32-reg accumulators, 4 CTAs/SM.
// Sym passes keep only tiles with tj >= ti/2 (rest fully below diagonal).
// ---------------------------------------------------------------------------
__global__ __launch_bounds__(256, 4)
void mmd_mma_kernel(const float* __restrict__ Nf, const float* __restrict__ Rf) {
    const int bid = blockIdx.x;

    int pass, ti, tj;
    if (bid < 2 * NSYM) {
        pass = bid < NSYM ? 0 : 1;
        int idx = bid - pass * NSYM;
        // rows come in pairs (2m, 2m+1), each with 64-m jobs starting at tj=m
        int m = 0;
        while (idx >= 2 * (64 - m)) { idx -= 2 * (64 - m); m++; }
        int second = idx >= (64 - m);
        if (second) idx -= (64 - m);
        ti = 2 * m + second;
        tj = m + idx;
    } else {
        pass = 2;
        int q = bid - 2 * NSYM;
        ti = q >> 6; tj = q & 63;
    }
    const bool sym = (pass < 2);

    const __nv_bfloat16 *Abf, *Bbf;
    const float *x2ha, *x2hb, *x2a, *x2b, *Af, *Bf;
    if (pass == 0)      { Abf = g_Nbf; Bbf = g_Nbf; x2ha = g_x2hN; x2hb = g_x2hN;
                          x2a = g_x2N; x2b = g_x2N; Af = Nf; Bf = Nf; }
    else if (pass == 1) { Abf = g_Rbf; Bbf = g_Rbf; x2ha = g_x2hR; x2hb = g_x2hR;
                          x2a = g_x2R; x2b = g_x2R; Af = Rf; Bf = Rf; }
    else                { Abf = g_Nbf; Bbf = g_Rbf; x2ha = g_x2hN; x2hb = g_x2hR;
                          x2a = g_x2N; x2b = g_x2R; Af = Nf; Bf = Rf; }

    extern __shared__ uint8_t dynsmem[];
    __shared__ float wsum[8];
    const int tid = threadIdx.x, wid = tid >> 5, lane = tid & 31;
    const uint32_t aS = smem_u32(dynsmem);
    const uint32_t bS = aS + A_BYTES;

    // ---- single load phase: rows are 128B = 8 chunks; 8 threads/row ----
    {
        const int chunk = tid & 7;
        const int rbase = tid >> 3;           // 0..31
        const uint8_t* Ag = (const uint8_t*)(Abf + (size_t)(ti * BM) * KS);
        const uint8_t* Bg = (const uint8_t*)(Bbf + (size_t)(tj * BN) * KS);
#pragma unroll
        for (int u = 0; u < 2; u++) {         // A: 64 rows
            int row = rbase + u * 32;
            CP16(aS + SWOFF8(row, chunk), Ag + (size_t)row * (KS * 2) + chunk * 16);
        }
#pragma unroll
        for (int u = 0; u < 4; u++) {         // B: 128 rows
            int row = rbase + u * 32;
            CP16(bS + SWOFF8(row, chunk), Bg + (size_t)row * (KS * 2) + chunk * 16);
        }
        asm volatile("cp.async.commit_group;" ::: "memory");
        asm volatile("cp.async.wait_group 0;" ::: "memory");
        __syncthreads();
    }

    float acc[2][4][4];
#pragma unroll
    for (int mi = 0; mi < 2; mi++)
#pragma unroll
        for (int ni = 0; ni < 4; ni++)
#pragma unroll
            for (int r = 0; r < 4; r++) acc[mi][ni][r] = 0.f;

    const int wm = (wid & 1) * 32;            // warp tile 32x32, layout 2x4
    const int wn = (wid >> 1) * 32;
    const int a_r = lane & 15, a_c = lane >> 4;
    const int b_r = lane & 7,  b_c = (lane >> 3) & 1;

    // ---- mainloop: zero barriers, 4 k-steps x 8 MMA ----
#pragma unroll 1
    for (int k = 0; k < KSTEPS; k++) {
        uint32_t a_frag[2][4], b_frag[4][2];
#pragma unroll
        for (int mi = 0; mi < 2; mi++)
            LDSM4(a_frag[mi], aS + SWOFF8(wm + mi * 16 + a_r, 2 * k + a_c));
#pragma unroll
        for (int ni = 0; ni < 4; ni++)
            LDSM2(b_frag[ni], bS + SWOFF8(wn + ni * 8 + b_r, 2 * k + b_c));
#pragma unroll
        for (int mi = 0; mi < 2; mi++)
#pragma unroll
            for (int ni = 0; ni < 4; ni++)
                MMA16816(acc[mi][ni], a_frag[mi], b_frag[ni]);
    }

    // ---- epilogue: partial-d2 screen; exact fp32 full-K recompute on pass ----
    const int qr = lane >> 2, qc = (lane & 3) * 2;
    float x2i[4], x2j[8];
#pragma unroll
    for (int mi = 0; mi < 2; mi++) {
        x2i[mi * 2 + 0] = x2ha[ti * BM + wm + mi * 16 + qr];
        x2i[mi * 2 + 1] = x2ha[ti * BM + wm + mi * 16 + qr + 8];
    }
#pragma unroll
    for (int ni = 0; ni < 4; ni++) {
        x2j[ni * 2 + 0] = x2hb[tj * BN + wn + ni * 8 + qc];
        x2j[ni * 2 + 1] = x2hb[tj * BN + wn + ni * 8 + qc + 1];
    }

    const bool diag = sym && (tj == (ti >> 1));   // tile intersects the diagonal
    const float base_w = sym ? 2.f : 1.f;
    float ssum = 0.f;
#pragma unroll
    for (int mi = 0; mi < 2; mi++) {
#pragma unroll
        for (int ni = 0; ni < 4; ni++) {
#pragma unroll
            for (int r = 0; r < 4; r++) {
                // partial d^2 over first 64 dims (lower bound of full d^2)
                float d2p = fmaf(-2.f, acc[mi][ni][r],
                                 x2i[mi * 2 + (r >> 1)] + x2j[ni * 2 + (r & 1)]);
                if (d2p < SCREEN_THRESH) {
                    int i = ti * BM + wm + mi * 16 + qr + (r >> 1) * 8;
                    int j = tj * BN + wn + ni * 8 + qc + (r & 1);
                    const float* ar = Af + (size_t)i * COLS;
                    const float* br = Bf + (size_t)j * COLS;
                    float pd = 0.f;
                    for (int k = 0; k < COLS; k += 4) {
                        float4 av = *(const float4*)(ar + k);
                        float4 bv = *(const float4*)(br + k);
                        pd = fmaf(av.x, bv.x, pd); pd = fmaf(av.y, bv.y, pd);
                        pd = fmaf(av.z, bv.z, pd); pd = fmaf(av.w, bv.w, pd);
                    }
                    float x2s = x2a[i] + x2b[j];
                    float d2f = fmaxf(fmaf(-2.f, pd, x2s), 0.f);
                    float w = base_w;
                    if (diag) w = (j > i) ? 2.f : ((j == i) ? 1.f : 0.f);
                    ssum += w * __expf(-d2f);
                }
            }
        }
    }

    // deterministic block reduction
#pragma unroll
    for (int o = 16; o > 0; o >>= 1) ssum += __shfl_xor_sync(0xffffffffu, ssum, o);
    if (lane == 0) wsum[wid] = ssum;
    __syncthreads();
    if (tid == 0) {
        float t = 0.f;
#pragma unroll
        for (int w = 0; w < 8; w++) t += wsum[w];
        g_part[bid] = t;
    }
}

// ---------------------------------------------------------------------------
// Final deterministic reduction + sqrt (single sweep, 3 accumulators).
// Slot ranges: [0,4160) NN, [4160,8320) RR, [8320,16512) NR.
// ---------------------------------------------------------------------------
__global__ void finalize_kernel(float* __restrict__ out) {
    __shared__ float sh0[256], sh1[256], sh2[256];
    const int tid = threadIdx.x;
    float s0 = 0.f, s1 = 0.f, s2 = 0.f;
    for (int idx = tid; idx < NBLK; idx += 256) {
        float v = g_part[idx];
        if (idx < NSYM) s0 += v;
        else if (idx < 2 * NSYM) s1 += v;
        else s2 += v;
    }
    sh0[tid] = s0; sh1[tid] = s1; sh2[tid] = s2;
    __syncthreads();
    for (int o = 128; o > 0; o >>= 1) {
        if (tid < o) {
            sh0[tid] += sh0[tid + o];
            sh1[tid] += sh1[tid + o];
            sh2[tid] += sh2[tid + o];
        }
        __syncthreads();
    }
    if (tid == 0) {
        double inv = 1.0 / ((double)ROWS * (double)ROWS);
        double mmd = ((double)sh0[0] + (double)sh1[0] - 2.0 * (double)sh2[0]) * inv;
        if (mmd < 0.0) mmd = 0.0;
        out[0] = (float)sqrt(mmd);
    }
}

// ---------------------------------------------------------------------------
extern "C" void kernel_launch(void* const* d_in, const int* in_sizes, int n_in,
                              void* d_out, int out_size) {
    const float* Nf = (const float*)d_in[0];
    const float* Rf = (const float*)d_in[1];
    float* out = (float*)d_out;
    (void)in_sizes; (void)n_in; (void)out_size;

    cudaFuncSetAttribute(mmd_mma_kernel,
                         cudaFuncAttributeMaxDynamicSharedMemorySize, DYN_SMEM);

    dim3 pgrid(ROWS / 8, 2, 1);
    prep_kernel<<<pgrid, 256>>>(Nf, Rf);

    mmd_mma_kernel<<<NBLK, 256, DYN_SMEM>>>(Nf, Rf);

    finalize_kernel<<<1, 256>>>(out);
}